// round 5
// baseline (speedup 1.0000x reference)
#include <cuda_runtime.h>
#include <cuda_bf16.h>
#include <cstdint>

// ---------------- problem constants ----------------
#define BB   4
#define NQ   8192
#define DM   256
#define HH   8
#define LL   4
#define DHD  32
#define NVV  5440
#define PCOLS 288
#define KD   256
#define NITER 8           // 256 / 32
#define BK   32

__device__ __constant__ int   c_Wl[LL]   = {64, 32, 16, 8};
__device__ __constant__ int   c_lsi[LL]  = {0, 4096, 5120, 5376};
__device__ __constant__ float c_inv[LL]  = {1.f/64.f, 1.f/32.f, 1.f/16.f, 1.f/8.f};

// ---------------- static device scratch ----------------
__device__ __nv_bfloat16 g_Whi[384 * KD];   // W^T hi (N-major, padded to 384 rows)
__device__ __nv_bfloat16 g_Wlo[384 * KD];   // W^T lo
__device__ float g_v[BB * NVV * DM];
__device__ float g_P[BB * NQ * PCOLS];
__device__ float g_mid[BB * NQ * DM];
__device__ float g_Wcat[DM * PCOLS];
__device__ float g_bcat[PCOLS];

// ---------------- helpers ----------------
__device__ __forceinline__ uint32_t smem_u32(const void* p) {
    uint32_t a;
    asm("{ .reg .u64 t; cvta.to.shared.u64 t, %1; cvt.u32.u64 %0, t; }" : "=r"(a) : "l"(p));
    return a;
}
__device__ __forceinline__ void cpa16(uint32_t s, const void* g) {
    asm volatile("cp.async.cg.shared.global [%0], [%1], 16;" :: "r"(s), "l"(g));
}
#define CPA_COMMIT() asm volatile("cp.async.commit_group;" ::: "memory")
#define SWZ64(x) ((x) ^ (((x) >> 3) & 0x30))

__device__ __forceinline__ void ldsm4(uint32_t& r0, uint32_t& r1, uint32_t& r2, uint32_t& r3,
                                      uint32_t addr) {
    asm volatile("ldmatrix.sync.aligned.m8n8.x4.shared.b16 {%0,%1,%2,%3}, [%4];"
                 : "=r"(r0), "=r"(r1), "=r"(r2), "=r"(r3) : "r"(addr));
}
__device__ __forceinline__ void mma16816(float* c, uint32_t a0, uint32_t a1, uint32_t a2,
                                         uint32_t a3, uint32_t b0, uint32_t b1) {
    asm volatile("mma.sync.aligned.m16n8k16.row.col.f32.bf16.bf16.f32 "
                 "{%0,%1,%2,%3}, {%4,%5,%6,%7}, {%8,%9}, {%0,%1,%2,%3};"
                 : "+f"(c[0]), "+f"(c[1]), "+f"(c[2]), "+f"(c[3])
                 : "r"(a0), "r"(a1), "r"(a2), "r"(a3), "r"(b0), "r"(b1));
}
__device__ __forceinline__ uint32_t prmt_hi(uint32_t a, uint32_t b) {
    uint32_t r;
    asm("prmt.b32 %0, %1, %2, 0x7632;" : "=r"(r) : "r"(a), "r"(b));
    return r;
}
__device__ __forceinline__ float trunc_bf(float f) {
    return __uint_as_float(__float_as_uint(f) & 0xFFFF0000u);
}
__device__ __forceinline__ uint32_t cvt_bf16x2(float hi, float lo) {
    uint32_t r;
    asm("cvt.rn.bf16x2.f32 %0, %1, %2;" : "=r"(r) : "f"(hi), "f"(lo));
    return r;
}
__device__ __forceinline__ void lds2(float& a, float& b, uint32_t addr) {
    asm volatile("ld.shared.v2.f32 {%0, %1}, [%2];" : "=f"(a), "=f"(b) : "r"(addr));
}

// ---------------- pack projection weights [256 x 288] ----------------
__global__ void pack_kernel(const float* __restrict__ Wt, const float* __restrict__ bt,
                            const float* __restrict__ Wf, const float* __restrict__ bf,
                            const float* __restrict__ Wl, const float* __restrict__ bl,
                            const float* __restrict__ Wp, const float* __restrict__ bp) {
    int i = blockIdx.x * blockDim.x + threadIdx.x;
    if (i < DM * PCOLS) {
        int r = i / PCOLS, c = i % PCOLS;
        float v;
        if      (c < 64)  v = Wt[r * 64  + c];
        else if (c < 128) v = Wf[r * 64  + (c - 64)];
        else if (c < 160) v = Wl[r * 32  + (c - 128)];
        else              v = Wp[r * 128 + (c - 160)];
        g_Wcat[i] = v;
    }
    if (i < PCOLS) {
        float v;
        if      (i < 64)  v = bt[i];
        else if (i < 128) v = bf[i - 64];
        else if (i < 160) v = bl[i - 128];
        else              v = bp[i - 160];
        g_bcat[i] = v;
    }
}

// W is [256 x N] row-major; produce split W^T hi/lo [384 x 256] (rows n>=N zero)
__global__ void convW_kernel(const float* __restrict__ W, int N) {
    int i = blockIdx.x * blockDim.x + threadIdx.x;
    if (i >= 384 * KD) return;
    int n = i >> 8, k = i & 255;
    float v = (n < N) ? W[k * N + n] : 0.f;
    __nv_bfloat16 hi = __float2bfloat16(v);
    __nv_bfloat16 lo = __float2bfloat16(v - __bfloat162float(hi));
    g_Whi[i] = hi;
    g_Wlo[i] = lo;
}

// ---------------- fp32-in bf16-mma GEMM: C[M,N] = A[M,256] * W^T + bias ----------------
// 128x128 tile, BK=32, 3-stage cp.async (96 KB smem), 8 warps (4M x 2N),
// in-register split: acc += Ahi*Whi + Alo*Whi + Ahi*Wlo
__global__ __launch_bounds__(256, 2)
void gemm_mma(const float* __restrict__ A,
              const float* __restrict__ bias, float* __restrict__ C,
              int M, int N) {
    extern __shared__ char smem[];                  // 3 * 32768
    const uint32_t sb = smem_u32(smem);
    const int tid = threadIdx.x, wid = tid >> 5, lane = tid & 31;
    const int wm = wid >> 1, wn = wid & 1;
    const int rowBase = blockIdx.y * 128, colBase = blockIdx.x * 128;

    // stage layout: A fp32 [128][32] at +0 (16KB), Whi at +16384 (8KB), Wlo at +24576 (8KB)
    auto load = [&](int j, int s) {
        uint32_t abase = sb + s * 32768;
        uint32_t hbase = abase + 16384;
        uint32_t lbase = abase + 24576;
        const float* ga = A + (size_t)rowBase * KD + j * BK;
        const __nv_bfloat16* gh = g_Whi + (size_t)colBase * KD + j * BK;
        const __nv_bfloat16* gl = g_Wlo + (size_t)colBase * KD + j * BK;
#pragma unroll
        for (int it = 0; it < 4; it++) {            // A: 1024 16B chunks
            int id = tid + it * 256;
            int r = id >> 3, cc = id & 7;
            cpa16(abase + r * 128 + ((cc ^ (r & 7)) << 4),
                  (const char*)(ga + (size_t)r * KD) + cc * 16);
        }
#pragma unroll
        for (int it = 0; it < 2; it++) {            // W tiles: 512 chunks each
            int id = tid + it * 256;
            int r = id >> 2, cc = id & 3;
            uint32_t sw = SWZ64(r * 64 + cc * 16);
            cpa16(hbase + sw, (const char*)(gh + (size_t)r * KD) + cc * 16);
            cpa16(lbase + sw, (const char*)(gl + (size_t)r * KD) + cc * 16);
        }
        CPA_COMMIT();
    };

    float acc[2][8][4];
#pragma unroll
    for (int mi = 0; mi < 2; mi++)
#pragma unroll
        for (int ni = 0; ni < 8; ni++)
#pragma unroll
            for (int q = 0; q < 4; q++) acc[mi][ni][q] = 0.f;

    load(0, 0); load(1, 1);

    const int aR = lane >> 2;                       // fragment row within 16
    const int aC = (lane & 3) * 2;                  // fragment k-pair base
    const int bRow = (lane & 7) + ((lane >> 4) << 3);
    const int bK   = ((lane >> 3) & 1) << 3;

    for (int i = 0; i < NITER; i++) {
        asm volatile("cp.async.wait_group 1;" ::: "memory");
        __syncthreads();
        if (i + 2 < NITER) load(i + 2, (i + 2) % 3);
        else CPA_COMMIT();

        uint32_t abase = sb + (i % 3) * 32768;
        uint32_t hbase = abase + 16384;
        uint32_t lbase = abase + 24576;
#pragma unroll
        for (int kk = 0; kk < BK; kk += 16) {
            // ---- A fragments: load fp32, split into hi/lo bf16x2 ----
            uint32_t ahi[2][4], alo[2][4];
#pragma unroll
            for (int mi = 0; mi < 2; mi++) {
#pragma unroll
                for (int p = 0; p < 4; p++) {       // (r,k),(r+8,k),(r,k+8),(r+8,k+8)
                    int row = wm * 32 + mi * 16 + aR + (p & 1) * 8;
                    int col = kk + aC + (p >> 1) * 8;
                    int g = col >> 2;
                    uint32_t addr = abase + row * 128 + ((g ^ (row & 7)) << 4) + ((col & 3) << 2);
                    float f0, f1;
                    lds2(f0, f1, addr);
                    ahi[mi][p] = prmt_hi(__float_as_uint(f0), __float_as_uint(f1));
                    alo[mi][p] = cvt_bf16x2(f1 - trunc_bf(f1), f0 - trunc_bf(f0));
                }
            }
            // ---- Whi fragments + 2 MMA streams ----
            uint32_t bh[4][4];
#pragma unroll
            for (int ng = 0; ng < 4; ng++) {
                int row = wn * 64 + ng * 16 + bRow;
                ldsm4(bh[ng][0], bh[ng][1], bh[ng][2], bh[ng][3],
                      hbase + SWZ64(row * 64 + (kk + bK) * 2));
            }
#pragma unroll
            for (int mi = 0; mi < 2; mi++)
#pragma unroll
                for (int ni = 0; ni < 8; ni++) {
                    int ng = ni >> 1, hf = ni & 1;
                    mma16816(acc[mi][ni], ahi[mi][0], ahi[mi][1], ahi[mi][2], ahi[mi][3],
                             bh[ng][hf * 2], bh[ng][hf * 2 + 1]);
                    mma16816(acc[mi][ni], alo[mi][0], alo[mi][1], alo[mi][2], alo[mi][3],
                             bh[ng][hf * 2], bh[ng][hf * 2 + 1]);
                }
            // ---- Wlo fragments + 1 MMA stream ----
            uint32_t bl[4][4];
#pragma unroll
            for (int ng = 0; ng < 4; ng++) {
                int row = wn * 64 + ng * 16 + bRow;
                ldsm4(bl[ng][0], bl[ng][1], bl[ng][2], bl[ng][3],
                      lbase + SWZ64(row * 64 + (kk + bK) * 2));
            }
#pragma unroll
            for (int mi = 0; mi < 2; mi++)
#pragma unroll
                for (int ni = 0; ni < 8; ni++) {
                    int ng = ni >> 1, hf = ni & 1;
                    mma16816(acc[mi][ni], ahi[mi][0], ahi[mi][1], ahi[mi][2], ahi[mi][3],
                             bl[ng][hf * 2], bl[ng][hf * 2 + 1]);
                }
        }
        __syncthreads();
    }

    // epilogue
    const int g = lane >> 2, tig = lane & 3;
#pragma unroll
    for (int mi = 0; mi < 2; mi++) {
        int r0 = rowBase + wm * 32 + mi * 16 + g;
        int r1 = r0 + 8;
#pragma unroll
        for (int ni = 0; ni < 8; ni++) {
            int c = colBase + wn * 64 + ni * 8 + tig * 2;
            if (c < N) {
                float bx = __ldg(&bias[c]), by = __ldg(&bias[c + 1]);
                float2 v0 = make_float2(acc[mi][ni][0] + bx, acc[mi][ni][1] + by);
                float2 v1 = make_float2(acc[mi][ni][2] + bx, acc[mi][ni][3] + by);
                *reinterpret_cast<float2*>(C + (size_t)r0 * N + c) = v0;
                *reinterpret_cast<float2*>(C + (size_t)r1 * N + c) = v1;
            }
        }
    }
}

// ---------------- deformable sampling with cell dedup ----------------
__device__ __forceinline__ float tanh_approx(float x) {
    float r;
    asm("tanh.approx.f32 %0, %1;" : "=f"(r) : "f"(x));
    return r;
}

// one warp per (b,q,h); lanes 0..3 each build the merged cell list for one level,
// then all 32 lanes gather (lane = channel within head).
__global__ __launch_bounds__(256)
void sample_kernel(const float* __restrict__ refp) {
    __shared__ int   s_idx[8][64];
    __shared__ float s_w[8][64];
    __shared__ int   s_cnt[8][4];

    const int warp = threadIdx.x >> 5;
    const int lane = threadIdx.x & 31;
    const int gid = blockIdx.x * 8 + warp;            // 0..B*NQ*H-1
    const int h  = gid & (HH - 1);
    const int bq = gid >> 3;
    const int b  = bq >> 13;                          // NQ=8192

    const float* __restrict__ P  = g_P + (size_t)bq * PCOLS;
    const float* __restrict__ rp = refp + (size_t)bq * (LL * 2);
    const int hL = h * LL;

    if (lane < 4) {
        const int l = lane;
        const int Wi = c_Wl[l];
        const float Wf = (float)Wi;
        const float inv = c_inv[l];
        const int start = c_lsi[l];

        // level softmax -> weight of this level
        float e0 = P[128 + hL + 0], e1 = P[128 + hL + 1];
        float e2 = P[128 + hL + 2], e3 = P[128 + hL + 3];
        float mx = fmaxf(fmaxf(e0, e1), fmaxf(e2, e3));
        float x0e = __expf(e0 - mx), x1e = __expf(e1 - mx);
        float x2e = __expf(e2 - mx), x3e = __expf(e3 - mx);
        float lw = (l == 0 ? x0e : l == 1 ? x1e : l == 2 ? x2e : x3e)
                   * __frcp_rn(x0e + x1e + x2e + x3e);

        // point softmax pw[kt*2+kf]
        const float* pp = P + 160 + (hL + l) * 4;
        float p0 = pp[0], p1 = pp[1], p2 = pp[2], p3 = pp[3];
        float pm = fmaxf(fmaxf(p0, p1), fmaxf(p2, p3));
        float q0 = __expf(p0 - pm), q1 = __expf(p1 - pm);
        float q2 = __expf(p2 - pm), q3 = __expf(p3 - pm);
        float pinv = __frcp_rn(q0 + q1 + q2 + q3);
        q0 *= pinv; q1 *= pinv; q2 *= pinv; q3 *= pinv;

        // merged x-cell list (time offsets)
        int   xc[4]; float xw0[4], xw1[4]; int nx = 0;
        int   yc[4]; float yw0[4], yw1[4]; int ny = 0;
#pragma unroll
        for (int kt = 0; kt < 2; kt++) {
            float t = tanh_approx(P[(hL + l) * 2 + kt]);
            float lx = fminf(fmaxf(rp[l * 2 + 0] + t * inv, 0.f), 1.f);
            float x = lx * Wf - 0.5f;
            float cf = floorf(x);
            float fx = x - cf;
            int c0 = (int)cf;
#pragma unroll
            for (int s = 0; s < 2; s++) {
                int c = c0 + s;
                float w = s ? fx : (1.f - fx);
                if (c >= 0 && c < Wi) {
                    bool found = false;
                    for (int i = 0; i < nx; i++)
                        if (xc[i] == c) { if (kt) xw1[i] += w; else xw0[i] += w; found = true; }
                    if (!found) {
                        xc[nx] = c;
                        xw0[nx] = kt ? 0.f : w;
                        xw1[nx] = kt ? w : 0.f;
                        nx++;
                    }
                }
            }
        }
#pragma unroll
        for (int kf = 0; kf < 2; kf++) {
            float f = tanh_approx(P[64 + (hL + l) * 2 + kf]);
            float ly = fminf(fmaxf(rp[l * 2 + 1] + f * inv, 0.f), 1.f);
            float y = ly * Wf - 0.5f;
            float cf = floorf(y);
            float fy = y - cf;
            int c0 = (int)cf;
#pragma unroll
            for (int s = 0; s < 2; s++) {
                int c = c0 + s;
                float w = s ? fy : (1.f - fy);
                if (c >= 0 && c < Wi) {
                    bool found = false;
                    for (int i = 0; i < ny; i++)
                        if (yc[i] == c) { if (kf) yw1[i] += w; else yw0[i] += w; found = true; }
                    if (!found) {
                        yc[ny] = c;
                        yw0[ny] = kf ? 0.f : w;
                        yw1[ny] = kf ? w : 0.f;
                        ny++;
                    }
                }
            }
        }
        // emit product cells: weight = lw * (xw0*(yw0*q0 + yw1*q1) + xw1*(yw0*q2 + yw1*q3))
        int cnt = 0;
        for (int i = 0; i < nx; i++) {
            float wx0 = xw0[i], wx1 = xw1[i];
            int xcc = start + xc[i];
            for (int j = 0; j < ny; j++) {
                float w = lw * (wx0 * (yw0[j] * q0 + yw1[j] * q1)
                              + wx1 * (yw0[j] * q2 + yw1[j] * q3));
                s_idx[warp][l * 16 + cnt] = xcc + yc[j] * Wi;
                s_w[warp][l * 16 + cnt]   = w;
                cnt++;
            }
        }
        s_cnt[warp][l] = cnt;
    }
    __syncwarp();

    const float* __restrict__ vb = g_v + (size_t)b * NVV * DM + h * DHD + lane;
    float acc = 0.f;
#pragma unroll
    for (int l = 0; l < 4; l++) {
        const int n = s_cnt[warp][l];
        for (int t = 0; t < n; t++) {
            acc += s_w[warp][l * 16 + t] * vb[(size_t)s_idx[warp][l * 16 + t] * DM];
        }
    }

    g_mid[(size_t)bq * DM + h * DHD + lane] = acc;
}

// ---------------- launch ----------------
extern "C" void kernel_launch(void* const* d_in, const int* in_sizes, int n_in,
                              void* d_out, int out_size) {
    const float* query  = (const float*)d_in[0];
    const float* refp   = (const float*)d_in[1];
    const float* value  = (const float*)d_in[2];
    const float* W_time = (const float*)d_in[5];
    const float* b_time = (const float*)d_in[6];
    const float* W_freq = (const float*)d_in[7];
    const float* b_freq = (const float*)d_in[8];
    const float* W_lvl  = (const float*)d_in[9];
    const float* b_lvl  = (const float*)d_in[10];
    const float* W_pt   = (const float*)d_in[11];
    const float* b_pt   = (const float*)d_in[12];
    const float* W_v    = (const float*)d_in[13];
    const float* b_v    = (const float*)d_in[14];
    const float* W_o    = (const float*)d_in[15];
    const float* b_o    = (const float*)d_in[16];
    float* out = (float*)d_out;

    float *p_v, *p_P, *p_mid, *p_Wcat, *p_bcat;
    cudaGetSymbolAddress((void**)&p_v,    g_v);
    cudaGetSymbolAddress((void**)&p_P,    g_P);
    cudaGetSymbolAddress((void**)&p_mid,  g_mid);
    cudaGetSymbolAddress((void**)&p_Wcat, g_Wcat);
    cudaGetSymbolAddress((void**)&p_bcat, g_bcat);

    const int GEMM_SMEM = 3 * 32768;   // 96 KB
    static bool attr_set = false;
    cudaFuncSetAttribute(gemm_mma, cudaFuncAttributeMaxDynamicSharedMemorySize, GEMM_SMEM);
    (void)attr_set;

    // 1) pack Wcat (fp32)
    pack_kernel<<<(DM * PCOLS + 255) / 256, 256>>>(W_time, b_time, W_freq, b_freq,
                                                   W_lvl, b_lvl, W_pt, b_pt);

    // 2) value GEMM: g_v = value @ W_v + b_v   [21760 x 256]
    convW_kernel<<<(384 * KD + 255) / 256, 256>>>(W_v, DM);
    {
        dim3 grid(2, (BB * NVV) / 128);
        gemm_mma<<<grid, 256, GEMM_SMEM>>>(value, b_v, p_v, BB * NVV, DM);
    }

    // 3) query projections: g_P = query @ Wcat + bcat   [32768 x 288]
    convW_kernel<<<(384 * KD + 255) / 256, 256>>>(p_Wcat, PCOLS);
    {
        dim3 grid(3, (BB * NQ) / 128);
        gemm_mma<<<grid, 256, GEMM_SMEM>>>(query, p_bcat, p_P, BB * NQ, PCOLS);
    }

    // 4) deformable sampling (merged-cell taps) -> g_mid fp32
    sample_kernel<<<(BB * NQ * HH) / 8, 256>>>(refp);

    // 5) output GEMM: out = mid @ W_o + b_o   [32768 x 256]
    convW_kernel<<<(384 * KD + 255) / 256, 256>>>(W_o, DM);
    {
        dim3 grid(2, (BB * NQ) / 128);
        gemm_mma<<<grid, 256, GEMM_SMEM>>>(p_mid, b_o, out, BB * NQ, DM);
    }
}